// round 16
// baseline (speedup 1.0000x reference)
#include <cuda_runtime.h>
#include <cuda_fp16.h>
#include <math.h>

// Problem constants
constexpr int B  = 2;
constexpr int S  = 2048;
constexpr int D  = 1024;
constexpr int H  = 16;
constexpr int HD = 64;
constexpr int BS = B * S;          // 4096 rows
constexpr int N_QKV = 3 * D;       // 3072

// Scratch (device globals — no allocation allowed). All fp16.
__device__ __half g_Q[B * H * S * HD];    // [b,h,s,hd]
__device__ __half g_K[B * H * S * HD];    // [b,h,s,hd]
__device__ __half g_V[B * H * S * HD];    // [b,h,hd,s]  TRANSPOSED
__device__ __half g_attn[BS * D];         // [b,s,d]
__device__ __half g_xh[BS * D];           // x in fp16
__device__ __half g_wqkvh[N_QKV * D];     // qkv_w in fp16
__device__ __half g_wouth[D * D];         // out_w in fp16

// ---------------------------------------------------------------------------
// Helpers
// ---------------------------------------------------------------------------
__device__ __forceinline__ unsigned smem_u32(const void* p) {
    unsigned a;
    asm("{ .reg .u64 t; cvta.to.shared.u64 t, %1; cvt.u32.u64 %0, t; }"
        : "=r"(a) : "l"(p));
    return a;
}
#define CP_ASYNC16(dst, src) \
    asm volatile("cp.async.cg.shared.global [%0], [%1], 16;" :: "r"(dst), "l"(src))
#define CP_COMMIT() asm volatile("cp.async.commit_group;")

// ldmatrix x4 (b16): each lane supplies the smem address of one 16B row.
__device__ __forceinline__ void ldsm4(unsigned& d0, unsigned& d1,
                                      unsigned& d2, unsigned& d3, unsigned addr) {
    asm volatile("ldmatrix.sync.aligned.m8n8.x4.shared.b16 {%0,%1,%2,%3}, [%4];"
        : "=r"(d0), "=r"(d1), "=r"(d2), "=r"(d3) : "r"(addr));
}

// D += A * B  (m16n8k16, fp16 in, fp32 accum)
__device__ __forceinline__ void mma16(float& d0, float& d1, float& d2, float& d3,
                                      unsigned a0, unsigned a1, unsigned a2, unsigned a3,
                                      unsigned b0, unsigned b1) {
    asm volatile(
        "mma.sync.aligned.m16n8k16.row.col.f32.f16.f16.f32 "
        "{%0,%1,%2,%3}, {%4,%5,%6,%7}, {%8,%9}, {%0,%1,%2,%3};"
        : "+f"(d0), "+f"(d1), "+f"(d2), "+f"(d3)
        : "r"(a0), "r"(a1), "r"(a2), "r"(a3), "r"(b0), "r"(b1));
}

__device__ __forceinline__ unsigned pack_h2(float lo, float hi) {
    __half2 h = __floats2half2_rn(lo, hi);
    return *(unsigned*)&h;
}

// ---------------------------------------------------------------------------
// Pre-convert pass: x, qkv_w, out_w -> fp16 copies.
// ---------------------------------------------------------------------------
__global__ __launch_bounds__(256) void half_pre(
    const float* __restrict__ x,
    const float* __restrict__ wqkv,
    const float* __restrict__ wout)
{
    const int NX = BS * D / 4, NW = N_QKV * D / 4, NO = D * D / 4;
    const int total = NX + NW + NO;
    for (int idx = blockIdx.x * blockDim.x + threadIdx.x; idx < total;
         idx += gridDim.x * blockDim.x) {
        const float4* src;
        __half2* dst;
        int off;
        if (idx < NX)            { src = (const float4*)x;    dst = (__half2*)g_xh;    off = idx; }
        else if (idx < NX + NW)  { src = (const float4*)wqkv; dst = (__half2*)g_wqkvh; off = idx - NX; }
        else                     { src = (const float4*)wout; dst = (__half2*)g_wouth; off = idx - NX - NW; }
        float4 v = src[off];
        dst[off * 2 + 0] = __floats2half2_rn(v.x, v.y);
        dst[off * 2 + 1] = __floats2half2_rn(v.z, v.w);
    }
}

// ---------------------------------------------------------------------------
// FP16 tensor-core GEMM (UNCHANGED from round 14/15 best).
// BM=BN=128, BK=64, 256 threads = 8 warps (4 M x 2 N), warp tile 32x64.
// Dynamic smem: 2 stages * 2 tiles * 128*72*2 = 73728 bytes.
// ---------------------------------------------------------------------------
template <bool SCATTER>
__global__ __launch_bounds__(256) void gemm_mma(
    const float* __restrict__ bias,
    float* __restrict__ C)
{
    constexpr int TILEB = 128 * 72 * 2;     // bytes per tile stage
    extern __shared__ __half smh[];
    const unsigned sA = smem_u32(smh);
    const unsigned sB = sA + 2 * TILEB;

    const __half* Ap = SCATTER ? g_xh    : g_attn;
    const __half* Wp = SCATTER ? g_wqkvh : g_wouth;

    const int t    = threadIdx.x;
    const int lane = t & 31;
    const int w    = t >> 5;
    const int g    = lane >> 2;     // 0..7
    const int tig  = lane & 3;      // 0..3
    const int wm   = w & 3;         // 0..3
    const int wn   = w >> 2;        // 0..1
    const int m0   = blockIdx.y * 128;
    const int n0   = blockIdx.x * 128;

    const int a_row = wm * 32 + ((lane >> 3) & 1) * 8 + (lane & 7);
    const unsigned aoff = (unsigned)(a_row * 144 + (lane >> 4) * 16);
    const int b_row = wn * 64 + ((lane >> 4) & 1) * 8 + (lane & 7);
    const unsigned boff = (unsigned)(b_row * 144 + ((lane >> 3) & 1) * 16);

    float acc[2][8][4];
    #pragma unroll
    for (int tm = 0; tm < 2; tm++)
        #pragma unroll
        for (int nt = 0; nt < 8; nt++)
            #pragma unroll
            for (int q = 0; q < 4; q++) acc[tm][nt][q] = 0.f;

    auto issue = [&](int k0, int buf) {
        #pragma unroll
        for (int r = 0; r < 4; r++) {
            const int u   = r * 256 + t;
            const int row = u >> 3;
            const int sg  = u & 7;
            const unsigned soff = (unsigned)(buf * TILEB + row * 144 + sg * 16);
            CP_ASYNC16(sA + soff, &Ap[(size_t)(m0 + row) * D + k0 + sg * 8]);
            CP_ASYNC16(sB + soff, &Wp[(size_t)(n0 + row) * D + k0 + sg * 8]);
        }
        CP_COMMIT();
    };

    constexpr int NK = D / 64;      // 16 k-chunks
    issue(0, 0);
    for (int i = 0; i < NK; i++) {
        if (i + 1 < NK) {
            issue((i + 1) * 64, (i + 1) & 1);
            asm volatile("cp.async.wait_group 1;");
        } else {
            asm volatile("cp.async.wait_group 0;");
        }
        __syncthreads();

        const unsigned Ab = sA + (unsigned)((i & 1) * TILEB);
        const unsigned Bb = sB + (unsigned)((i & 1) * TILEB);

        unsigned af[2][2][4];
        unsigned bf[2][8][2];
        auto load_frags = [&](int ks, int pb) {
            ldsm4(af[pb][0][0], af[pb][0][1], af[pb][0][2], af[pb][0][3],
                  Ab + aoff + (unsigned)ks * 32u);
            ldsm4(af[pb][1][0], af[pb][1][1], af[pb][1][2], af[pb][1][3],
                  Ab + aoff + 16u * 144u + (unsigned)ks * 32u);
            #pragma unroll
            for (int np = 0; np < 4; np++) {
                unsigned d0, d1, d2, d3;
                ldsm4(d0, d1, d2, d3,
                      Bb + boff + (unsigned)(np * 16 * 144) + (unsigned)ks * 32u);
                bf[pb][np * 2][0]     = d0; bf[pb][np * 2][1]     = d1;
                bf[pb][np * 2 + 1][0] = d2; bf[pb][np * 2 + 1][1] = d3;
            }
        };

        load_frags(0, 0);
        #pragma unroll
        for (int ks = 0; ks < 4; ks++) {
            const int cur = ks & 1;
            if (ks < 3) load_frags(ks + 1, cur ^ 1);
            #pragma unroll
            for (int tm = 0; tm < 2; tm++)
                #pragma unroll
                for (int nt = 0; nt < 8; nt++)
                    mma16(acc[tm][nt][0], acc[tm][nt][1], acc[tm][nt][2], acc[tm][nt][3],
                          af[cur][tm][0], af[cur][tm][1], af[cur][tm][2], af[cur][tm][3],
                          bf[cur][nt][0], bf[cur][nt][1]);
        }
        __syncthreads();
    }

    #pragma unroll
    for (int tm = 0; tm < 2; tm++) {
        const int r0 = m0 + wm * 32 + tm * 16 + g;
        #pragma unroll
        for (int nt = 0; nt < 8; nt++) {
            const int c = n0 + wn * 64 + nt * 8 + 2 * tig;
            const float b0 = bias[c], b1 = bias[c + 1];
            const float v00 = acc[tm][nt][0] + b0, v01 = acc[tm][nt][1] + b1;
            const float v10 = acc[tm][nt][2] + b0, v11 = acc[tm][nt][3] + b1;
            if (SCATTER) {
                const int which = c >> 10;          // 0=Q,1=K,2=V
                const int dd = c & (D - 1);
                const int h  = dd >> 6;
                const int hi = dd & (HD - 1);       // even
                const int bb0 = r0 >> 11, ss0 = r0 & (S - 1);
                const int bb1 = (r0 + 8) >> 11, ss1 = (r0 + 8) & (S - 1);
                if (which == 2) {
                    __half* dv0 = g_V + ((size_t)(bb0 * H + h) * HD) * S;
                    dv0[(size_t)hi * S + ss0]       = __float2half_rn(v00);
                    dv0[(size_t)(hi + 1) * S + ss0] = __float2half_rn(v01);
                    __half* dv1 = g_V + ((size_t)(bb1 * H + h) * HD) * S;
                    dv1[(size_t)hi * S + ss1]       = __float2half_rn(v10);
                    dv1[(size_t)(hi + 1) * S + ss1] = __float2half_rn(v11);
                } else {
                    __half* dst = (which == 0) ? g_Q : g_K;
                    *(__half2*)&dst[(((size_t)(bb0 * H + h) * S) + ss0) * HD + hi] =
                        __floats2half2_rn(v00, v01);
                    *(__half2*)&dst[(((size_t)(bb1 * H + h) * S) + ss1) * HD + hi] =
                        __floats2half2_rn(v10, v11);
                }
            } else {
                *(float2*)&C[(size_t)r0 * D + c]       = make_float2(v00, v01);
                *(float2*)&C[(size_t)(r0 + 8) * D + c] = make_float2(v10, v11);
            }
        }
    }
}

// ---------------------------------------------------------------------------
// FP16 tensor-core attention (quirk: scores[i,j] = k_i . q_j, scale 1/8).
// JT=128 (NJ=16).  NEW: __launch_bounds__(256, 3) to raise occupancy to
// 3 CTAs/SM (regs capped at 85; smem 3 x 71.68KB = 215KB fits).
// Dynamic smem: 2 stages * (18432 + 17408) = 71680 bytes.
// ---------------------------------------------------------------------------
constexpr int QTB = 128 * 144;         // Q tile bytes (18432)
constexpr int VTB = 64 * 272;          // V tile bytes (17408)

__global__ __launch_bounds__(256, 3) void flash_attn_mma()
{
    extern __shared__ __half smh[];
    const unsigned sQ = smem_u32(smh);
    const unsigned sV = sQ + 2 * QTB;

    const int bh = blockIdx.x;                 // b*H + h
    const int i0 = blockIdx.y * 128;
    const int t    = threadIdx.x;
    const int lane = t & 31;
    const int w    = t >> 5;
    const int g    = lane >> 2;
    const int tig  = lane & 3;

    const __half* Kp = g_K + (size_t)bh * S * HD;
    const __half* Qp = g_Q + (size_t)bh * S * HD;
    const __half* Vp = g_V + (size_t)bh * HD * S;   // transposed

    // Q LDSM (B-op of mma1): rows j (stride 144B)
    const unsigned qoff = (unsigned)((lane & 7) * 144 + (lane >> 3) * 16);
    // V LDSM (B-op of mma2, VT rows=hd, stride 272B)
    const unsigned voff = (unsigned)(((lane & 7) + ((lane >> 4) & 1) * 8) * 272
                                     + ((lane >> 3) & 1) * 16);

    // K A-fragments: 4 x k16 covering hd=64; raw half2 loads from gmem
    unsigned ak[4][4];
    {
        const int kr = i0 + w * 16 + g;
        #pragma unroll
        for (int ks = 0; ks < 4; ks++) {
            ak[ks][0] = *(const unsigned*)&Kp[(size_t)kr * HD + ks * 16 + 2 * tig];
            ak[ks][1] = *(const unsigned*)&Kp[(size_t)(kr + 8) * HD + ks * 16 + 2 * tig];
            ak[ks][2] = *(const unsigned*)&Kp[(size_t)kr * HD + ks * 16 + 8 + 2 * tig];
            ak[ks][3] = *(const unsigned*)&Kp[(size_t)(kr + 8) * HD + ks * 16 + 8 + 2 * tig];
        }
    }

    float o[8][4];
    #pragma unroll
    for (int dt = 0; dt < 8; dt++)
        #pragma unroll
        for (int q = 0; q < 4; q++) o[dt][q] = 0.f;
    float l0 = 0.f, l1 = 0.f;
    const float C1 = 0.18033688011112042f;     // log2(e)/8

    // Copy map per stage: Q 128 rows x 8 segs (1024) + V 64 rows x 16 segs (1024)
    auto issue = [&](int j0, int buf) {
        #pragma unroll
        for (int r = 0; r < 4; r++) {
            const int u = r * 256 + t;
            const int qrow = u >> 3, qsg = u & 7;
            CP_ASYNC16(sQ + (unsigned)(buf * QTB + qrow * 144 + qsg * 16),
                       &Qp[(size_t)(j0 + qrow) * HD + qsg * 8]);
            const int vrow = u >> 4, vsg = u & 15;
            CP_ASYNC16(sV + (unsigned)(buf * VTB + vrow * 272 + vsg * 16),
                       &Vp[(size_t)vrow * S + j0 + vsg * 8]);
        }
        CP_COMMIT();
    };

    constexpr int NJ = S / 128;    // 16 tiles
    issue(0, 0);
    for (int i = 0; i < NJ; i++) {
        if (i + 1 < NJ) {
            issue((i + 1) * 128, (i + 1) & 1);
            asm volatile("cp.async.wait_group 1;");
        } else {
            asm volatile("cp.async.wait_group 0;");
        }
        __syncthreads();

        const unsigned Qbb = sQ + (unsigned)((i & 1) * QTB);
        const unsigned Vbb = sV + (unsigned)((i & 1) * VTB);

        #pragma unroll
        for (int jt = 0; jt < 8; jt++) {       // 16 j's per sub-iteration
            // --- V fragments first (independent; hide under mma1+softmax)
            unsigned vf[8][2];
            #pragma unroll
            for (int p = 0; p < 4; p++) {
                unsigned d0, d1, d2, d3;
                ldsm4(d0, d1, d2, d3,
                      Vbb + voff + (unsigned)(p * 16 * 272) + (unsigned)jt * 32u);
                vf[2 * p][0]     = d0; vf[2 * p][1]     = d1;
                vf[2 * p + 1][0] = d2; vf[2 * p + 1][1] = d3;
            }
            // --- mma1 for two 8-j n-tiles
            float c[2][4];
            #pragma unroll
            for (int nt = 0; nt < 2; nt++) {
                unsigned qf[4][2];
                #pragma unroll
                for (int kb = 0; kb < 2; kb++) {
                    unsigned d0, d1, d2, d3;
                    ldsm4(d0, d1, d2, d3,
                          Qbb + qoff + (unsigned)((jt * 2 + nt) * 8 * 144)
                              + (unsigned)kb * 64u);
                    qf[2 * kb][0]     = d0; qf[2 * kb][1]     = d1;
                    qf[2 * kb + 1][0] = d2; qf[2 * kb + 1][1] = d3;
                }
                c[nt][0] = c[nt][1] = c[nt][2] = c[nt][3] = 0.f;
                #pragma unroll
                for (int ks = 0; ks < 4; ks++)
                    mma16(c[nt][0], c[nt][1], c[nt][2], c[nt][3],
                          ak[ks][0], ak[ks][1], ak[ks][2], ak[ks][3],
                          qf[ks][0], qf[ks][1]);
            }
            // --- softmax numerators
            float p00 = exp2f(c[0][0] * C1), p01 = exp2f(c[0][1] * C1);
            float p02 = exp2f(c[0][2] * C1), p03 = exp2f(c[0][3] * C1);
            float p10 = exp2f(c[1][0] * C1), p11 = exp2f(c[1][1] * C1);
            float p12 = exp2f(c[1][2] * C1), p13 = exp2f(c[1][3] * C1);
            l0 += p00 + p01 + p10 + p11;
            l1 += p02 + p03 + p12 + p13;
            // --- P A-fragment: concatenation of the two C-frags (free)
            const unsigned pa0 = pack_h2(p00, p01);
            const unsigned pa1 = pack_h2(p02, p03);
            const unsigned pa2 = pack_h2(p10, p11);
            const unsigned pa3 = pack_h2(p12, p13);
            // --- mma2: O += P(16x16) x V(16 j x 64 d)
            #pragma unroll
            for (int dt = 0; dt < 8; dt++)
                mma16(o[dt][0], o[dt][1], o[dt][2], o[dt][3],
                      pa0, pa1, pa2, pa3, vf[dt][0], vf[dt][1]);
        }
        __syncthreads();
    }

    // Reduce l across the 4 lanes sharing a row, normalize, write out (fp16)
    l0 += __shfl_xor_sync(0xffffffff, l0, 1);
    l0 += __shfl_xor_sync(0xffffffff, l0, 2);
    l1 += __shfl_xor_sync(0xffffffff, l1, 1);
    l1 += __shfl_xor_sync(0xffffffff, l1, 2);
    const float inv0 = 1.f / l0;
    const float inv1 = 1.f / l1;

    const int bb = bh >> 4;
    const int h  = bh & (H - 1);
    const int r0 = i0 + w * 16 + g;
    __half* d0 = g_attn + ((size_t)(bb * S + r0)) * D + h * HD;
    __half* d1 = g_attn + ((size_t)(bb * S + r0 + 8)) * D + h * HD;
    #pragma unroll
    for (int dt = 0; dt < 8; dt++) {
        *(__half2*)&d0[dt * 8 + 2 * tig] =
            __floats2half2_rn(o[dt][0] * inv0, o[dt][1] * inv0);
        *(__half2*)&d1[dt * 8 + 2 * tig] =
            __floats2half2_rn(o[dt][2] * inv1, o[dt][3] * inv1);
    }
}

// ---------------------------------------------------------------------------
extern "C" void kernel_launch(void* const* d_in, const int* in_sizes, int n_in,
                              void* d_out, int out_size)
{
    const float* x     = (const float*)d_in[0];
    const float* qkv_w = (const float*)d_in[1];
    const float* qkv_b = (const float*)d_in[2];
    const float* out_w = (const float*)d_in[3];
    const float* out_b = (const float*)d_in[4];
    float* out = (float*)d_out;

    constexpr int GEMM_SMEM = 2 * 2 * 128 * 72 * 2;   // 73728
    constexpr int ATTN_SMEM = 2 * (QTB + VTB);        // 71680
    cudaFuncSetAttribute(gemm_mma<true>,  cudaFuncAttributeMaxDynamicSharedMemorySize, GEMM_SMEM);
    cudaFuncSetAttribute(gemm_mma<false>, cudaFuncAttributeMaxDynamicSharedMemorySize, GEMM_SMEM);
    cudaFuncSetAttribute(flash_attn_mma,  cudaFuncAttributeMaxDynamicSharedMemorySize, ATTN_SMEM);

    // 0) Pre-convert x and weights to fp16
    half_pre<<<2048, 256>>>(x, qkv_w, out_w);

    // 1) QKV projection (fp16 mma), scatter to Q/K/VT
    gemm_mma<true><<<dim3(N_QKV / 128, BS / 128), 256, GEMM_SMEM>>>(qkv_b, nullptr);

    // 2) Attention (quirk: K is the query side), fp16 mma, JT=128, occ=3
    flash_attn_mma<<<dim3(B * H, S / 128), 256, ATTN_SMEM>>>();

    // 3) Output projection (fp32 out)
    gemm_mma<false><<<dim3(D / 128, BS / 128), 256, GEMM_SMEM>>>(out_b, out);
}